// round 6
// baseline (speedup 1.0000x reference)
#include <cuda_runtime.h>

#define N_NODES  50000
#define N_EDGES  800000
#define IN_CH    128
#define HID      64
#define N_GRAPHS 512
#define OUT_CH   10

// ---------------- scratch (static device memory; no allocations) ------------
__device__ float g_bufA[N_NODES * HID];   // y (pre-agg features)
__device__ float g_bufZ[N_NODES * HID];   // Z (combined, post-relu)
__device__ float g_bufT[N_NODES * HID];   // T (mid-MLP)
__device__ float g_pooled[N_GRAPHS * HID];
__device__ int   g_deg[N_NODES];
__device__ int   g_start[N_NODES + 1];
__device__ int   g_cursor[N_NODES];
__device__ int   g_srcs[N_EDGES];

// ============================================================================
// K1: y0 = x @ w0a  (K=128). Tail: zero deg histogram; block 0 zeroes pooled.
// ============================================================================
__global__ void __launch_bounds__(256) gemm_in_kernel(
    const float* __restrict__ A, const float* __restrict__ W,
    float* __restrict__ out, int* __restrict__ deg, float* __restrict__ pooled)
{
    __shared__ float sX[64][68];
    __shared__ float sW[64][64];

    const int tid = threadIdx.x;
    const int tc = tid & 15;
    const int tr = tid >> 4;
    const int row0 = blockIdx.x * 64;

    float acc[4][4] = {};

    for (int kc = 0; kc < IN_CH; kc += 64) {
#pragma unroll
        for (int i = 0; i < 16; ++i) {
            int idx = tid + i * 256;
            sW[idx >> 6][idx & 63] = W[(kc + (idx >> 6)) * 64 + (idx & 63)];
        }
#pragma unroll
        for (int i = 0; i < 16; ++i) {
            int idx = tid + i * 256;
            int r = idx >> 6, kk = idx & 63;
            int row = row0 + r;
            sX[r][kk] = (row < N_NODES) ? A[(size_t)row * IN_CH + kc + kk] : 0.f;
        }
        __syncthreads();

#pragma unroll
        for (int k = 0; k < 64; k += 4) {
            float4 wv0 = *(const float4*)&sW[k + 0][tc * 4];
            float4 wv1 = *(const float4*)&sW[k + 1][tc * 4];
            float4 wv2 = *(const float4*)&sW[k + 2][tc * 4];
            float4 wv3 = *(const float4*)&sW[k + 3][tc * 4];
#pragma unroll
            for (int i = 0; i < 4; ++i) {
                float4 xv = *(const float4*)&sX[tr * 4 + i][k];
                acc[i][0] += xv.x * wv0.x + xv.y * wv1.x + xv.z * wv2.x + xv.w * wv3.x;
                acc[i][1] += xv.x * wv0.y + xv.y * wv1.y + xv.z * wv2.y + xv.w * wv3.y;
                acc[i][2] += xv.x * wv0.z + xv.y * wv1.z + xv.z * wv2.z + xv.w * wv3.z;
                acc[i][3] += xv.x * wv0.w + xv.y * wv1.w + xv.z * wv2.w + xv.w * wv3.w;
            }
        }
        __syncthreads();
    }

#pragma unroll
    for (int i = 0; i < 4; ++i) {
        int row = row0 + tr * 4 + i;
        if (row < N_NODES)
            *(float4*)&out[(size_t)row * 64 + tc * 4] =
                make_float4(acc[i][0], acc[i][1], acc[i][2], acc[i][3]);
    }

    // zero degree histogram (782 blocks x 64 covers 50048 >= 50000)
    if (tid < 64) {
        int i = row0 + tid;
        if (i < N_NODES) deg[i] = 0;
    }
    if (blockIdx.x == 0) {
        const float4 z4 = make_float4(0.f, 0.f, 0.f, 0.f);
        for (int i = tid; i < N_GRAPHS * HID / 4; i += 256)
            ((float4*)pooled)[i] = z4;
    }
}

// ============================================================================
// CSR build (batched 8 edges/thread for MLP)
// ============================================================================
__global__ void __launch_bounds__(256) hist_kernel(
    const int* __restrict__ ei, int* __restrict__ deg)
{
    int e0 = (blockIdx.x * blockDim.x + threadIdx.x) * 8;
    if (e0 >= N_EDGES) return;
    int d[8];
#pragma unroll
    for (int u = 0; u < 8; ++u) d[u] = __ldg(&ei[N_EDGES + e0 + u]);
#pragma unroll
    for (int u = 0; u < 8; ++u) atomicAdd(&deg[d[u]], 1);
}

__global__ void __launch_bounds__(1024) scan_kernel(
    const int* __restrict__ deg, int* __restrict__ start, int* __restrict__ cursor)
{
    __shared__ int part[1024];
    const int tid = threadIdx.x;
    const int CHUNK = (N_NODES + 1023) / 1024;   // 49
    const int base = tid * CHUNK;

    int s = 0;
    for (int i = 0; i < CHUNK; ++i) {
        int idx = base + i;
        if (idx < N_NODES) s += deg[idx];
    }
    part[tid] = s;
    __syncthreads();
    for (int off = 1; off < 1024; off <<= 1) {
        int v = (tid >= off) ? part[tid - off] : 0;
        __syncthreads();
        part[tid] += v;
        __syncthreads();
    }
    int run = part[tid] - s;   // exclusive prefix
    for (int i = 0; i < CHUNK; ++i) {
        int idx = base + i;
        if (idx < N_NODES) {
            start[idx] = run;
            cursor[idx] = run;
            run += deg[idx];
        }
    }
    if (tid == 1023) start[N_NODES] = run;
}

__global__ void __launch_bounds__(256) scatter_kernel(
    const int* __restrict__ ei, int* __restrict__ cursor, int* __restrict__ srcs)
{
    int e0 = (blockIdx.x * blockDim.x + threadIdx.x) * 8;
    if (e0 >= N_EDGES) return;
    int s[8], d[8];
#pragma unroll
    for (int u = 0; u < 8; ++u) {
        s[u] = __ldg(&ei[e0 + u]);
        d[u] = __ldg(&ei[N_EDGES + e0 + u]);
    }
#pragma unroll
    for (int u = 0; u < 8; ++u) {
        int pos = atomicAdd(&cursor[d[u]], 1);
        srcs[pos] = s[u];
    }
}

// ============================================================================
// agg+combine (gather, MLP=8):
//   Z[node] = relu((1+eps)*y[node] + sum_{src in CSR(node)} y[src] + preb)
// 16 threads per node (one float4 chunk each). No atomics; write-once.
// ============================================================================
__global__ void __launch_bounds__(256) agg_combine_kernel(
    const float* __restrict__ y, const int* __restrict__ start,
    const int* __restrict__ srcs, const float* __restrict__ epsp,
    const float* __restrict__ preb, float* __restrict__ z)
{
    const int tid = threadIdx.x;
    const int node = blockIdx.x * 16 + (tid >> 4);
    const int c4 = tid & 15;
    if (node >= N_NODES) return;

    const int s0 = __ldg(&start[node]);
    const int s1 = __ldg(&start[node + 1]);

    float4 a0 = make_float4(0.f, 0.f, 0.f, 0.f);
    float4 a1 = make_float4(0.f, 0.f, 0.f, 0.f);
    int j = s0;
    for (; j + 8 <= s1; j += 8) {
        int idx[8];
#pragma unroll
        for (int u = 0; u < 8; ++u) idx[u] = __ldg(&srcs[j + u]);
        float4 v[8];
#pragma unroll
        for (int u = 0; u < 8; ++u)
            v[u] = *(const float4*)(y + (size_t)idx[u] * 64 + c4 * 4);
#pragma unroll
        for (int u = 0; u < 8; u += 2) {
            a0.x += v[u].x;   a0.y += v[u].y;   a0.z += v[u].z;   a0.w += v[u].w;
            a1.x += v[u+1].x; a1.y += v[u+1].y; a1.z += v[u+1].z; a1.w += v[u+1].w;
        }
    }
    for (; j < s1; ++j) {
        int i0 = __ldg(&srcs[j]);
        float4 v0 = *(const float4*)(y + (size_t)i0 * 64 + c4 * 4);
        a0.x += v0.x; a0.y += v0.y; a0.z += v0.z; a0.w += v0.w;
    }
    a0.x += a1.x; a0.y += a1.y; a0.z += a1.z; a0.w += a1.w;

    const float epsf = 1.0f + __ldg(&epsp[0]);
    float4 self = *(const float4*)(y + (size_t)node * 64 + c4 * 4);
    float4 pb   = *(const float4*)(preb + c4 * 4);
    float4 o;
    o.x = fmaxf(fmaf(epsf, self.x, a0.x) + pb.x, 0.f);
    o.y = fmaxf(fmaf(epsf, self.y, a0.y) + pb.y, 0.f);
    o.z = fmaxf(fmaf(epsf, self.z, a0.z) + pb.z, 0.f);
    o.w = fmaxf(fmaf(epsf, self.w, a0.w) + pb.w, 0.f);
    *(float4*)(z + (size_t)node * 64 + c4 * 4) = o;
}

// ============================================================================
// GEMM 64x64:  out = EPI ? relu(A@W + bias) : A@W
// ============================================================================
template <bool EPI>
__global__ void __launch_bounds__(256, 5) gemm64_kernel(
    const float* __restrict__ A, const float* __restrict__ W,
    const float* __restrict__ bias, float* __restrict__ out)
{
    __shared__ float sX[64][68];
    __shared__ float sW[64][64];

    const int tid = threadIdx.x;
    const int tc = tid & 15;
    const int tr = tid >> 4;
    const int row0 = blockIdx.x * 64;

#pragma unroll
    for (int i = 0; i < 16; ++i) {
        int idx = tid + i * 256;
        sW[idx >> 6][idx & 63] = W[idx];
    }
#pragma unroll
    for (int i = 0; i < 16; ++i) {
        int idx = tid + i * 256;
        int r = idx >> 6, kk = idx & 63;
        int row = row0 + r;
        sX[r][kk] = (row < N_NODES) ? A[(size_t)row * 64 + kk] : 0.f;
    }
    __syncthreads();

    float acc[4][4] = {};
#pragma unroll
    for (int k = 0; k < 64; k += 4) {
        float4 wv0 = *(const float4*)&sW[k + 0][tc * 4];
        float4 wv1 = *(const float4*)&sW[k + 1][tc * 4];
        float4 wv2 = *(const float4*)&sW[k + 2][tc * 4];
        float4 wv3 = *(const float4*)&sW[k + 3][tc * 4];
#pragma unroll
        for (int i = 0; i < 4; ++i) {
            float4 xv = *(const float4*)&sX[tr * 4 + i][k];
            acc[i][0] += xv.x * wv0.x + xv.y * wv1.x + xv.z * wv2.x + xv.w * wv3.x;
            acc[i][1] += xv.x * wv0.y + xv.y * wv1.y + xv.z * wv2.y + xv.w * wv3.y;
            acc[i][2] += xv.x * wv0.z + xv.y * wv1.z + xv.z * wv2.z + xv.w * wv3.z;
            acc[i][3] += xv.x * wv0.w + xv.y * wv1.w + xv.z * wv2.w + xv.w * wv3.w;
        }
    }

#pragma unroll
    for (int i = 0; i < 4; ++i) {
        int row = row0 + tr * 4 + i;
        if (row < N_NODES) {
            float4 o = make_float4(acc[i][0], acc[i][1], acc[i][2], acc[i][3]);
            if (EPI) {
                const float4 bv = *(const float4*)&bias[tc * 4];
                o.x = fmaxf(o.x + bv.x, 0.f);
                o.y = fmaxf(o.y + bv.y, 0.f);
                o.z = fmaxf(o.z + bv.z, 0.f);
                o.w = fmaxf(o.w + bv.w, 0.f);
            }
            *(float4*)&out[(size_t)row * 64 + tc * 4] = o;
        }
    }
}

// ============================================================================
// GEMM + pool:  h = relu(A@W + bias); pooled[batch[row]] += h[row]
// ============================================================================
__global__ void __launch_bounds__(256, 5) gemm_pool_kernel(
    const float* __restrict__ A, const float* __restrict__ W,
    const float* __restrict__ bias, const int* __restrict__ batch,
    float* __restrict__ pooled)
{
    __shared__ float sX[64][68];
    __shared__ float sW[64][64];

    const int tid = threadIdx.x;
    const int tc = tid & 15;
    const int tr = tid >> 4;
    const int row0 = blockIdx.x * 64;

#pragma unroll
    for (int i = 0; i < 16; ++i) {
        int idx = tid + i * 256;
        sW[idx >> 6][idx & 63] = W[idx];
    }
#pragma unroll
    for (int i = 0; i < 16; ++i) {
        int idx = tid + i * 256;
        int r = idx >> 6, kk = idx & 63;
        int row = row0 + r;
        sX[r][kk] = (row < N_NODES) ? A[(size_t)row * 64 + kk] : 0.f;
    }
    __syncthreads();

    float acc[4][4] = {};
#pragma unroll
    for (int k = 0; k < 64; k += 4) {
        float4 wv0 = *(const float4*)&sW[k + 0][tc * 4];
        float4 wv1 = *(const float4*)&sW[k + 1][tc * 4];
        float4 wv2 = *(const float4*)&sW[k + 2][tc * 4];
        float4 wv3 = *(const float4*)&sW[k + 3][tc * 4];
#pragma unroll
        for (int i = 0; i < 4; ++i) {
            float4 xv = *(const float4*)&sX[tr * 4 + i][k];
            acc[i][0] += xv.x * wv0.x + xv.y * wv1.x + xv.z * wv2.x + xv.w * wv3.x;
            acc[i][1] += xv.x * wv0.y + xv.y * wv1.y + xv.z * wv2.y + xv.w * wv3.y;
            acc[i][2] += xv.x * wv0.z + xv.y * wv1.z + xv.z * wv2.z + xv.w * wv3.z;
            acc[i][3] += xv.x * wv0.w + xv.y * wv1.w + xv.z * wv2.w + xv.w * wv3.w;
        }
    }

    const float4 bv = *(const float4*)&bias[tc * 4];
#pragma unroll
    for (int i = 0; i < 4; ++i) {
        int row = row0 + tr * 4 + i;
        if (row < N_NODES) {
            int g = __ldg(&batch[row]);
            float4 o;
            o.x = fmaxf(acc[i][0] + bv.x, 0.f);
            o.y = fmaxf(acc[i][1] + bv.y, 0.f);
            o.z = fmaxf(acc[i][2] + bv.z, 0.f);
            o.w = fmaxf(acc[i][3] + bv.w, 0.f);
            float* p = pooled + (size_t)g * 64 + tc * 4;
            asm volatile("red.global.add.v4.f32 [%0], {%1,%2,%3,%4};"
                         :: "l"(p), "f"(o.x), "f"(o.y), "f"(o.z), "f"(o.w) : "memory");
        }
    }
}

// ============================================================================
// head: logits + log_softmax
// ============================================================================
__global__ void __launch_bounds__(256) head_kernel(
    const float* __restrict__ pooled, const float* __restrict__ fcw,
    const float* __restrict__ fcb, float* __restrict__ out)
{
    int g = blockIdx.x * blockDim.x + threadIdx.x;
    if (g >= N_GRAPHS) return;
    float logit[OUT_CH];
#pragma unroll
    for (int j = 0; j < OUT_CH; ++j) logit[j] = __ldg(&fcb[j]);
#pragma unroll 8
    for (int k = 0; k < HID; ++k) {
        float p = pooled[g * HID + k];
#pragma unroll
        for (int j = 0; j < OUT_CH; ++j)
            logit[j] += p * __ldg(&fcw[k * OUT_CH + j]);
    }
    float m = logit[0];
#pragma unroll
    for (int j = 1; j < OUT_CH; ++j) m = fmaxf(m, logit[j]);
    float s = 0.f;
#pragma unroll
    for (int j = 0; j < OUT_CH; ++j) s += __expf(logit[j] - m);
    float ls = m + logf(s);
#pragma unroll
    for (int j = 0; j < OUT_CH; ++j) out[g * OUT_CH + j] = logit[j] - ls;
}

// ---------------- launch ----------------------------------------------------
extern "C" void kernel_launch(void* const* d_in, const int* in_sizes, int n_in,
                              void* d_out, int out_size)
{
    const float* x    = (const float*)d_in[0];
    const int*   ei   = (const int*)d_in[1];
    const int*   batch= (const int*)d_in[2];
    const float* eps0 = (const float*)d_in[3];
    const float* w0a  = (const float*)d_in[4];
    const float* b0a  = (const float*)d_in[5];
    const float* w0b  = (const float*)d_in[6];
    const float* b0b  = (const float*)d_in[7];
    const float* eps1 = (const float*)d_in[8];
    const float* w1a  = (const float*)d_in[9];
    const float* b1a  = (const float*)d_in[10];
    const float* w1b  = (const float*)d_in[11];
    const float* b1b  = (const float*)d_in[12];
    const float* fcw  = (const float*)d_in[13];
    const float* fcb  = (const float*)d_in[14];
    float*       out  = (float*)d_out;

    float *bufA, *bufZ, *bufT, *pooled;
    int *deg, *start, *cursor, *srcs;
    cudaGetSymbolAddress((void**)&bufA, g_bufA);
    cudaGetSymbolAddress((void**)&bufZ, g_bufZ);
    cudaGetSymbolAddress((void**)&bufT, g_bufT);
    cudaGetSymbolAddress((void**)&pooled, g_pooled);
    cudaGetSymbolAddress((void**)&deg, g_deg);
    cudaGetSymbolAddress((void**)&start, g_start);
    cudaGetSymbolAddress((void**)&cursor, g_cursor);
    cudaGetSymbolAddress((void**)&srcs, g_srcs);

    const int gemm_blocks = (N_NODES + 63) / 64;            // 782
    const int e8_blocks   = (N_EDGES / 8 + 255) / 256;      // 391
    const int agg_blocks  = (N_NODES + 15) / 16;            // 3125

    // K1: y0 = x @ w0a ; zero deg + pooled
    gemm_in_kernel<<<gemm_blocks, 256>>>(x, w0a, bufA, deg, pooled);
    // CSR build
    hist_kernel<<<e8_blocks, 256>>>(ei, deg);
    scan_kernel<<<1, 1024>>>(deg, start, cursor);
    scatter_kernel<<<e8_blocks, 256>>>(ei, cursor, srcs);

    // Layer 0
    agg_combine_kernel<<<agg_blocks, 256>>>(bufA, start, srcs, eps0, b0a, bufZ);
    gemm64_kernel<true><<<gemm_blocks, 256>>>(bufZ, w0b, b0b, bufT);
    gemm64_kernel<false><<<gemm_blocks, 256>>>(bufT, w1a, nullptr, bufA);

    // Layer 1
    agg_combine_kernel<<<agg_blocks, 256>>>(bufA, start, srcs, eps1, b1a, bufZ);
    gemm_pool_kernel<<<gemm_blocks, 256>>>(bufZ, w1b, b1b, batch, pooled);

    // Head
    head_kernel<<<2, 256>>>(pooled, fcw, fcb, out);
}

// round 8
// speedup vs baseline: 1.2119x; 1.2119x over previous
#include <cuda_runtime.h>
#include <cstdint>

#define N_NODES  50000
#define N_EDGES  800000
#define IN_CH    128
#define HID      64
#define N_GRAPHS 512
#define OUT_CH   10

// ---------------- scratch (static device memory; no allocations) ------------
__device__ float g_bufA[N_NODES * HID];   // y (pre-agg features)
__device__ float g_bufB[N_NODES * HID];   // agg buffer (reduce target)
__device__ float g_bufC[N_NODES * HID];   // h0
__device__ float g_pooled[N_GRAPHS * HID];

// ============================================================================
// K1: y0 = x @ w0a  (K=128). Tail: zero agg buffer rows; block 0 zeroes pooled.
// ============================================================================
__global__ void __launch_bounds__(256) gemm_in_kernel(
    const float* __restrict__ A, const float* __restrict__ W,
    float* __restrict__ out, float* __restrict__ aggz, float* __restrict__ pooled)
{
    __shared__ float sX[64][68];
    __shared__ float sW[64][64];

    const int tid = threadIdx.x;
    const int tc = tid & 15;
    const int tr = tid >> 4;
    const int row0 = blockIdx.x * 64;

    float acc[4][4] = {};

    for (int kc = 0; kc < IN_CH; kc += 64) {
#pragma unroll
        for (int i = 0; i < 16; ++i) {
            int idx = tid + i * 256;
            sW[idx >> 6][idx & 63] = W[(kc + (idx >> 6)) * 64 + (idx & 63)];
        }
#pragma unroll
        for (int i = 0; i < 16; ++i) {
            int idx = tid + i * 256;
            int r = idx >> 6, kk = idx & 63;
            int row = row0 + r;
            sX[r][kk] = (row < N_NODES) ? A[(size_t)row * IN_CH + kc + kk] : 0.f;
        }
        __syncthreads();

#pragma unroll
        for (int k = 0; k < 64; k += 4) {
            float4 wv0 = *(const float4*)&sW[k + 0][tc * 4];
            float4 wv1 = *(const float4*)&sW[k + 1][tc * 4];
            float4 wv2 = *(const float4*)&sW[k + 2][tc * 4];
            float4 wv3 = *(const float4*)&sW[k + 3][tc * 4];
#pragma unroll
            for (int i = 0; i < 4; ++i) {
                float4 xv = *(const float4*)&sX[tr * 4 + i][k];
                acc[i][0] += xv.x * wv0.x + xv.y * wv1.x + xv.z * wv2.x + xv.w * wv3.x;
                acc[i][1] += xv.x * wv0.y + xv.y * wv1.y + xv.z * wv2.y + xv.w * wv3.y;
                acc[i][2] += xv.x * wv0.z + xv.y * wv1.z + xv.z * wv2.z + xv.w * wv3.z;
                acc[i][3] += xv.x * wv0.w + xv.y * wv1.w + xv.z * wv2.w + xv.w * wv3.w;
            }
        }
        __syncthreads();
    }

#pragma unroll
    for (int i = 0; i < 4; ++i) {
        int row = row0 + tr * 4 + i;
        if (row < N_NODES)
            *(float4*)&out[(size_t)row * 64 + tc * 4] =
                make_float4(acc[i][0], acc[i][1], acc[i][2], acc[i][3]);
    }

    const float4 z4 = make_float4(0.f, 0.f, 0.f, 0.f);
#pragma unroll
    for (int i = 0; i < 4; ++i) {
        int idx = tid + i * 256;
        int row = row0 + (idx >> 4);
        if (row < N_NODES)
            *(float4*)&aggz[(size_t)row * 64 + (idx & 15) * 4] = z4;
    }
    if (blockIdx.x == 0) {
        for (int i = tid; i < N_GRAPHS * HID / 4; i += 256)
            ((float4*)pooled)[i] = z4;
    }
}

// ============================================================================
// Edge aggregation via TMA bulk-reduce:
//   one cp.reduce.async.bulk (256B = full 64-ch row) per edge, instead of
//   16x red.global.add.v4 (which sits on the 1.29 cyc/16B LTS atomic floor).
// Each half-warp owns one edge per iteration: 16 lanes gather y[src] into a
// double-buffered smem slot; lane 0 of the half-warp issues the bulk reduce.
// 3125 blocks * 16 half-warps = 50000 half-warps; 16 iters covers 800000
// edges exactly (no bounds checks needed).
// ============================================================================
#define AGG_BLOCKS 3125
__global__ void __launch_bounds__(256) edge_agg_tma_kernel(
    const float* __restrict__ y, const int* __restrict__ ei,
    float* __restrict__ agg)
{
    __shared__ __align__(16) float stage[32][64];   // 8 warps * 4 slots * 256B = 8KB

    const int tid    = threadIdx.x;
    const int lane16 = tid & 15;
    const int warp   = tid >> 5;
    const int half   = (tid >> 4) & 1;
    const int slot0  = warp * 4 + half * 2;
    const int hw     = blockIdx.x * 16 + (tid >> 4);   // 0..49999
    const int TOT    = AGG_BLOCKS * 16;                // 50000

#pragma unroll 1
    for (int it = 0; it < N_EDGES / TOT; ++it) {       // 16 iterations
        const int e = hw + it * TOT;                   // always < N_EDGES
        const int b = it & 1;

        // before overwriting slot b (last used 2 iters ago), ensure its
        // bulk-reduce has finished reading smem (keep <=1 group pending-read)
        if (it >= 2 && lane16 == 0)
            asm volatile("cp.async.bulk.wait_group.read 1;" ::: "memory");
        __syncwarp();

        int src = __ldg(&ei[e]);
        float4 v = *(const float4*)(y + (size_t)src * 64 + lane16 * 4);
        *(float4*)&stage[slot0 + b][lane16 * 4] = v;
        __syncwarp();

        if (lane16 == 0) {
            int dst = __ldg(&ei[N_EDGES + e]);
            float* gdst = agg + (size_t)dst * 64;
            unsigned int saddr = (unsigned int)__cvta_generic_to_shared(&stage[slot0 + b][0]);
            asm volatile("fence.proxy.async.shared::cta;" ::: "memory");
            asm volatile(
                "cp.reduce.async.bulk.global.shared::cta.bulk_group.add.f32 "
                "[%0], [%1], 256;"
                :: "l"(gdst), "r"(saddr) : "memory");
            asm volatile("cp.async.bulk.commit_group;" ::: "memory");
        }
    }
    // full completion (global writes done) before kernel exit
    if (lane16 == 0)
        asm volatile("cp.async.bulk.wait_group 0;" ::: "memory");
}

// ============================================================================
// K3: combine + GEMM:  out = relu( relu((1+eps)*A + G + preb) @ W + bias )
// ============================================================================
__global__ void __launch_bounds__(256) combine_gemm_kernel(
    const float* __restrict__ A, const float* __restrict__ G,
    const float* __restrict__ epsp, const float* __restrict__ preb,
    const float* __restrict__ W, const float* __restrict__ bias,
    float* __restrict__ out)
{
    __shared__ float sX[64][68];
    __shared__ float sW[64][64];

    const int tid = threadIdx.x;
    const int tc = tid & 15;
    const int tr = tid >> 4;
    const int row0 = blockIdx.x * 64;
    const float epsf = 1.0f + __ldg(&epsp[0]);

#pragma unroll
    for (int i = 0; i < 16; ++i) {
        int idx = tid + i * 256;
        sW[idx >> 6][idx & 63] = W[idx];
    }
#pragma unroll
    for (int i = 0; i < 16; ++i) {
        int idx = tid + i * 256;
        int r = idx >> 6, kk = idx & 63;
        int row = row0 + r;
        float v = 0.f;
        if (row < N_NODES) {
            size_t off = (size_t)row * 64 + kk;
            v = fmaxf(fmaf(epsf, A[off], G[off]) + preb[kk], 0.f);
        }
        sX[r][kk] = v;
    }
    __syncthreads();

    float acc[4][4] = {};
#pragma unroll
    for (int k = 0; k < 64; k += 4) {
        float4 wv0 = *(const float4*)&sW[k + 0][tc * 4];
        float4 wv1 = *(const float4*)&sW[k + 1][tc * 4];
        float4 wv2 = *(const float4*)&sW[k + 2][tc * 4];
        float4 wv3 = *(const float4*)&sW[k + 3][tc * 4];
#pragma unroll
        for (int i = 0; i < 4; ++i) {
            float4 xv = *(const float4*)&sX[tr * 4 + i][k];
            acc[i][0] += xv.x * wv0.x + xv.y * wv1.x + xv.z * wv2.x + xv.w * wv3.x;
            acc[i][1] += xv.x * wv0.y + xv.y * wv1.y + xv.z * wv2.y + xv.w * wv3.y;
            acc[i][2] += xv.x * wv0.z + xv.y * wv1.z + xv.z * wv2.z + xv.w * wv3.z;
            acc[i][3] += xv.x * wv0.w + xv.y * wv1.w + xv.z * wv2.w + xv.w * wv3.w;
        }
    }

    const float4 bv = *(const float4*)&bias[tc * 4];
#pragma unroll
    for (int i = 0; i < 4; ++i) {
        int row = row0 + tr * 4 + i;
        if (row < N_NODES) {
            float4 o;
            o.x = fmaxf(acc[i][0] + bv.x, 0.f);
            o.y = fmaxf(acc[i][1] + bv.y, 0.f);
            o.z = fmaxf(acc[i][2] + bv.z, 0.f);
            o.w = fmaxf(acc[i][3] + bv.w, 0.f);
            *(float4*)&out[(size_t)row * 64 + tc * 4] = o;
        }
    }
}

// ============================================================================
// K4: plain GEMM 64x64: out = A @ W ; tail: re-zero agg buffer rows
// ============================================================================
__global__ void __launch_bounds__(256) gemm64_zero_kernel(
    const float* __restrict__ A, const float* __restrict__ W,
    float* __restrict__ out, float* __restrict__ aggz)
{
    __shared__ float sX[64][68];
    __shared__ float sW[64][64];

    const int tid = threadIdx.x;
    const int tc = tid & 15;
    const int tr = tid >> 4;
    const int row0 = blockIdx.x * 64;

#pragma unroll
    for (int i = 0; i < 16; ++i) {
        int idx = tid + i * 256;
        sW[idx >> 6][idx & 63] = W[idx];
    }
#pragma unroll
    for (int i = 0; i < 16; ++i) {
        int idx = tid + i * 256;
        int r = idx >> 6, kk = idx & 63;
        int row = row0 + r;
        sX[r][kk] = (row < N_NODES) ? A[(size_t)row * 64 + kk] : 0.f;
    }
    __syncthreads();

    float acc[4][4] = {};
#pragma unroll
    for (int k = 0; k < 64; k += 4) {
        float4 wv0 = *(const float4*)&sW[k + 0][tc * 4];
        float4 wv1 = *(const float4*)&sW[k + 1][tc * 4];
        float4 wv2 = *(const float4*)&sW[k + 2][tc * 4];
        float4 wv3 = *(const float4*)&sW[k + 3][tc * 4];
#pragma unroll
        for (int i = 0; i < 4; ++i) {
            float4 xv = *(const float4*)&sX[tr * 4 + i][k];
            acc[i][0] += xv.x * wv0.x + xv.y * wv1.x + xv.z * wv2.x + xv.w * wv3.x;
            acc[i][1] += xv.x * wv0.y + xv.y * wv1.y + xv.z * wv2.y + xv.w * wv3.y;
            acc[i][2] += xv.x * wv0.z + xv.y * wv1.z + xv.z * wv2.z + xv.w * wv3.z;
            acc[i][3] += xv.x * wv0.w + xv.y * wv1.w + xv.z * wv2.w + xv.w * wv3.w;
        }
    }

#pragma unroll
    for (int i = 0; i < 4; ++i) {
        int row = row0 + tr * 4 + i;
        if (row < N_NODES)
            *(float4*)&out[(size_t)row * 64 + tc * 4] =
                make_float4(acc[i][0], acc[i][1], acc[i][2], acc[i][3]);
    }

    const float4 z4 = make_float4(0.f, 0.f, 0.f, 0.f);
#pragma unroll
    for (int i = 0; i < 4; ++i) {
        int idx = tid + i * 256;
        int row = row0 + (idx >> 4);
        if (row < N_NODES)
            *(float4*)&aggz[(size_t)row * 64 + (idx & 15) * 4] = z4;
    }
}

// ============================================================================
// K6: combine + GEMM + pool:  h = relu(relu((1+eps)*A+G+preb) @ W + bias)
//     pooled[batch[row]] += h[row]   (h never hits global)
// ============================================================================
__global__ void __launch_bounds__(256) combine_gemm_pool_kernel(
    const float* __restrict__ A, const float* __restrict__ G,
    const float* __restrict__ epsp, const float* __restrict__ preb,
    const float* __restrict__ W, const float* __restrict__ bias,
    const int* __restrict__ batch, float* __restrict__ pooled)
{
    __shared__ float sX[64][68];
    __shared__ float sW[64][64];

    const int tid = threadIdx.x;
    const int tc = tid & 15;
    const int tr = tid >> 4;
    const int row0 = blockIdx.x * 64;
    const float epsf = 1.0f + __ldg(&epsp[0]);

#pragma unroll
    for (int i = 0; i < 16; ++i) {
        int idx = tid + i * 256;
        sW[idx >> 6][idx & 63] = W[idx];
    }
#pragma unroll
    for (int i = 0; i < 16; ++i) {
        int idx = tid + i * 256;
        int r = idx >> 6, kk = idx & 63;
        int row = row0 + r;
        float v = 0.f;
        if (row < N_NODES) {
            size_t off = (size_t)row * 64 + kk;
            v = fmaxf(fmaf(epsf, A[off], G[off]) + preb[kk], 0.f);
        }
        sX[r][kk] = v;
    }
    __syncthreads();

    float acc[4][4] = {};
#pragma unroll
    for (int k = 0; k < 64; k += 4) {
        float4 wv0 = *(const float4*)&sW[k + 0][tc * 4];
        float4 wv1 = *(const float4*)&sW[k + 1][tc * 4];
        float4 wv2 = *(const float4*)&sW[k + 2][tc * 4];
        float4 wv3 = *(const float4*)&sW[k + 3][tc * 4];
#pragma unroll
        for (int i = 0; i < 4; ++i) {
            float4 xv = *(const float4*)&sX[tr * 4 + i][k];
            acc[i][0] += xv.x * wv0.x + xv.y * wv1.x + xv.z * wv2.x + xv.w * wv3.x;
            acc[i][1] += xv.x * wv0.y + xv.y * wv1.y + xv.z * wv2.y + xv.w * wv3.y;
            acc[i][2] += xv.x * wv0.z + xv.y * wv1.z + xv.z * wv2.z + xv.w * wv3.z;
            acc[i][3] += xv.x * wv0.w + xv.y * wv1.w + xv.z * wv2.w + xv.w * wv3.w;
        }
    }

    const float4 bv = *(const float4*)&bias[tc * 4];
#pragma unroll
    for (int i = 0; i < 4; ++i) {
        int row = row0 + tr * 4 + i;
        if (row < N_NODES) {
            int g = __ldg(&batch[row]);
            float4 o;
            o.x = fmaxf(acc[i][0] + bv.x, 0.f);
            o.y = fmaxf(acc[i][1] + bv.y, 0.f);
            o.z = fmaxf(acc[i][2] + bv.z, 0.f);
            o.w = fmaxf(acc[i][3] + bv.w, 0.f);
            float* p = pooled + (size_t)g * 64 + tc * 4;
            asm volatile("red.global.add.v4.f32 [%0], {%1,%2,%3,%4};"
                         :: "l"(p), "f"(o.x), "f"(o.y), "f"(o.z), "f"(o.w) : "memory");
        }
    }
}

// ============================================================================
// K7: head: logits + log_softmax
// ============================================================================
__global__ void __launch_bounds__(256) head_kernel(
    const float* __restrict__ pooled, const float* __restrict__ fcw,
    const float* __restrict__ fcb, float* __restrict__ out)
{
    int g = blockIdx.x * blockDim.x + threadIdx.x;
    if (g >= N_GRAPHS) return;
    float logit[OUT_CH];
#pragma unroll
    for (int j = 0; j < OUT_CH; ++j) logit[j] = __ldg(&fcb[j]);
#pragma unroll 8
    for (int k = 0; k < HID; ++k) {
        float p = pooled[g * HID + k];
#pragma unroll
        for (int j = 0; j < OUT_CH; ++j)
            logit[j] += p * __ldg(&fcw[k * OUT_CH + j]);
    }
    float m = logit[0];
#pragma unroll
    for (int j = 1; j < OUT_CH; ++j) m = fmaxf(m, logit[j]);
    float s = 0.f;
#pragma unroll
    for (int j = 0; j < OUT_CH; ++j) s += __expf(logit[j] - m);
    float ls = m + logf(s);
#pragma unroll
    for (int j = 0; j < OUT_CH; ++j) out[g * OUT_CH + j] = logit[j] - ls;
}

// ---------------- launch ----------------------------------------------------
extern "C" void kernel_launch(void* const* d_in, const int* in_sizes, int n_in,
                              void* d_out, int out_size)
{
    const float* x    = (const float*)d_in[0];
    const int*   ei   = (const int*)d_in[1];
    const int*   batch= (const int*)d_in[2];
    const float* eps0 = (const float*)d_in[3];
    const float* w0a  = (const float*)d_in[4];
    const float* b0a  = (const float*)d_in[5];
    const float* w0b  = (const float*)d_in[6];
    const float* b0b  = (const float*)d_in[7];
    const float* eps1 = (const float*)d_in[8];
    const float* w1a  = (const float*)d_in[9];
    const float* b1a  = (const float*)d_in[10];
    const float* w1b  = (const float*)d_in[11];
    const float* b1b  = (const float*)d_in[12];
    const float* fcw  = (const float*)d_in[13];
    const float* fcb  = (const float*)d_in[14];
    float*       out  = (float*)d_out;

    float *bufA, *bufB, *bufC, *pooled;
    cudaGetSymbolAddress((void**)&bufA, g_bufA);
    cudaGetSymbolAddress((void**)&bufB, g_bufB);
    cudaGetSymbolAddress((void**)&bufC, g_bufC);
    cudaGetSymbolAddress((void**)&pooled, g_pooled);

    const int gemm_blocks = (N_NODES + 63) / 64;   // 782

    // K1: y0 = x @ w0a ; zero bufB + pooled
    gemm_in_kernel<<<gemm_blocks, 256>>>(x, w0a, bufA, bufB, pooled);
    // K2: agg0 = bulk-reduce scatter of y0
    edge_agg_tma_kernel<<<AGG_BLOCKS, 256>>>(bufA, ei, bufB);
    // K3: h0 = relu(relu(combine0) @ w0b + b0b)
    combine_gemm_kernel<<<gemm_blocks, 256>>>(bufA, bufB, eps0, b0a, w0b, b0b, bufC);
    // K4: y1 = h0 @ w1a ; re-zero bufB
    gemm64_zero_kernel<<<gemm_blocks, 256>>>(bufC, w1a, bufA, bufB);
    // K5: agg1 = bulk-reduce scatter of y1
    edge_agg_tma_kernel<<<AGG_BLOCKS, 256>>>(bufA, ei, bufB);
    // K6: h1 = relu(relu(combine1) @ w1b + b1b) ; pool into pooled
    combine_gemm_pool_kernel<<<gemm_blocks, 256>>>(bufA, bufB, eps1, b1a, w1b, b1b, batch, pooled);
    // K7: logits + log_softmax
    head_kernel<<<2, 256>>>(pooled, fcw, fcb, out);
}

// round 9
// speedup vs baseline: 1.3766x; 1.1358x over previous
#include <cuda_runtime.h>
#include <cstdint>

#define N_NODES  50000
#define N_EDGES  800000
#define IN_CH    128
#define HID      64
#define N_GRAPHS 512
#define OUT_CH   10

#define TILE_ROWS 128
#define SX_STRIDE 68                    // 16B-aligned, conflict-free for row-diff 1
#define SMEM_BYTES (TILE_ROWS * SX_STRIDE * 4 + 64 * 64 * 4)   // 51200

// ---------------- scratch (static device memory; no allocations) ------------
__device__ float g_bufA[N_NODES * HID];   // y (pre-agg features)
__device__ float g_bufB[N_NODES * HID];   // agg buffer (atomics target)
__device__ float g_bufC[N_NODES * HID];   // h0
__device__ float g_pooled[N_GRAPHS * HID];

// ============================================================================
// Shared GEMM core pieces (128x64 tile, 256 threads, 8x4 per thread)
// Thread t: cols [tc*4, tc*4+4), rows {tr + 16*i}, tc = t&15, tr = t>>4.
// ============================================================================

// compute acc += sX-chunk @ sW  (one 64-wide K chunk)
#define GEMM_COMPUTE_CHUNK(sX, sW)                                            \
    _Pragma("unroll 4")                                                       \
    for (int k = 0; k < 64; k += 4) {                                         \
        float4 wv0 = *(const float4*)&sW[(k + 0) * 64 + tc * 4];              \
        float4 wv1 = *(const float4*)&sW[(k + 1) * 64 + tc * 4];              \
        float4 wv2 = *(const float4*)&sW[(k + 2) * 64 + tc * 4];              \
        float4 wv3 = *(const float4*)&sW[(k + 3) * 64 + tc * 4];              \
        _Pragma("unroll")                                                     \
        for (int i = 0; i < 8; ++i) {                                         \
            float4 xv = *(const float4*)&sX[(tr + 16 * i) * SX_STRIDE + k];   \
            acc[i][0] += xv.x * wv0.x + xv.y * wv1.x + xv.z * wv2.x + xv.w * wv3.x; \
            acc[i][1] += xv.x * wv0.y + xv.y * wv1.y + xv.z * wv2.y + xv.w * wv3.y; \
            acc[i][2] += xv.x * wv0.z + xv.y * wv1.z + xv.z * wv2.z + xv.w * wv3.z; \
            acc[i][3] += xv.x * wv0.w + xv.y * wv1.w + xv.z * wv2.w + xv.w * wv3.w; \
        }                                                                     \
    }

// load 64x64 W chunk (row-major, contiguous) into sW via float4
#define LOAD_W_CHUNK(sW, Wptr)                                                \
    _Pragma("unroll")                                                         \
    for (int i = 0; i < 4; ++i) {                                             \
        int f4 = tid + i * 256;            /* 1024 float4s */                 \
        *(float4*)&sW[f4 * 4] = *(const float4*)&(Wptr)[f4 * 4];              \
    }

// ============================================================================
// K1: y0 = x @ w0a  (K=128). Tail: zero agg rows; block 0 zeroes pooled.
// ============================================================================
__global__ void __launch_bounds__(256) gemm_in_kernel(
    const float* __restrict__ A, const float* __restrict__ W,
    float* __restrict__ out, float* __restrict__ aggz, float* __restrict__ pooled)
{
    extern __shared__ float smem[];
    float* sX = smem;
    float* sW = smem + TILE_ROWS * SX_STRIDE;

    const int tid = threadIdx.x;
    const int tc = tid & 15;
    const int tr = tid >> 4;
    const int row0 = blockIdx.x * TILE_ROWS;

    float acc[8][4] = {};

    for (int kc = 0; kc < IN_CH; kc += 64) {
        LOAD_W_CHUNK(sW, W + kc * 64)
#pragma unroll
        for (int i = 0; i < 8; ++i) {
            int f4 = tid + i * 256;            // 2048 float4s = 128 rows x 16
            int r = f4 >> 4, c4 = f4 & 15;
            int row = row0 + r;
            float4 v = make_float4(0.f, 0.f, 0.f, 0.f);
            if (row < N_NODES)
                v = *(const float4*)&A[(size_t)row * IN_CH + kc + c4 * 4];
            *(float4*)&sX[r * SX_STRIDE + c4 * 4] = v;
        }
        __syncthreads();
        GEMM_COMPUTE_CHUNK(sX, sW)
        __syncthreads();
    }

#pragma unroll
    for (int i = 0; i < 8; ++i) {
        int row = row0 + tr + 16 * i;
        if (row < N_NODES)
            *(float4*)&out[(size_t)row * 64 + tc * 4] =
                make_float4(acc[i][0], acc[i][1], acc[i][2], acc[i][3]);
    }

    const float4 z4 = make_float4(0.f, 0.f, 0.f, 0.f);
#pragma unroll
    for (int i = 0; i < 8; ++i) {
        int f4 = tid + i * 256;
        int row = row0 + (f4 >> 4);
        if (row < N_NODES)
            *(float4*)&aggz[(size_t)row * 64 + (f4 & 15) * 4] = z4;
    }
    if (blockIdx.x == 0) {
        for (int i = tid; i < N_GRAPHS * HID / 4; i += 256)
            ((float4*)pooled)[i] = z4;
    }
}

// ============================================================================
// Edge aggregation (8 edges/thread, red.global.add.v4) — proven R5 kernel.
// ============================================================================
#define E_PER 8
__global__ void __launch_bounds__(256) edge_agg_kernel(
    const float* __restrict__ y, const int* __restrict__ ei,
    float* __restrict__ agg)
{
    const int t = blockIdx.x * blockDim.x + threadIdx.x;
    const int c4 = t & 15;
    const int eb = (t >> 4) * E_PER;
    if (eb >= N_EDGES) return;

    int s[E_PER], d[E_PER];
#pragma unroll
    for (int j = 0; j < E_PER; ++j) {
        s[j] = __ldg(&ei[eb + j]);
        d[j] = __ldg(&ei[N_EDGES + eb + j]);
    }
    float4 v[E_PER];
#pragma unroll
    for (int j = 0; j < E_PER; ++j)
        v[j] = *(const float4*)(y + (size_t)s[j] * 64 + c4 * 4);
#pragma unroll
    for (int j = 0; j < E_PER; ++j) {
        float* p = agg + (size_t)d[j] * 64 + c4 * 4;
        asm volatile("red.global.add.v4.f32 [%0], {%1,%2,%3,%4};"
                     :: "l"(p), "f"(v[j].x), "f"(v[j].y), "f"(v[j].z), "f"(v[j].w)
                     : "memory");
    }
}

// ============================================================================
// K3: combine + GEMM:  out = relu( relu((1+eps)*A + G + preb) @ W + bias )
// ============================================================================
__global__ void __launch_bounds__(256) combine_gemm_kernel(
    const float* __restrict__ A, const float* __restrict__ G,
    const float* __restrict__ epsp, const float* __restrict__ preb,
    const float* __restrict__ W, const float* __restrict__ bias,
    float* __restrict__ out)
{
    extern __shared__ float smem[];
    float* sX = smem;
    float* sW = smem + TILE_ROWS * SX_STRIDE;

    const int tid = threadIdx.x;
    const int tc = tid & 15;
    const int tr = tid >> 4;
    const int row0 = blockIdx.x * TILE_ROWS;
    const float epsf = 1.0f + __ldg(&epsp[0]);

    LOAD_W_CHUNK(sW, W)
#pragma unroll
    for (int i = 0; i < 8; ++i) {
        int f4 = tid + i * 256;
        int r = f4 >> 4, c4 = f4 & 15;
        int row = row0 + r;
        float4 v = make_float4(0.f, 0.f, 0.f, 0.f);
        if (row < N_NODES) {
            float4 a = *(const float4*)&A[(size_t)row * 64 + c4 * 4];
            float4 g = *(const float4*)&G[(size_t)row * 64 + c4 * 4];
            float4 pb = *(const float4*)&preb[c4 * 4];
            v.x = fmaxf(fmaf(epsf, a.x, g.x) + pb.x, 0.f);
            v.y = fmaxf(fmaf(epsf, a.y, g.y) + pb.y, 0.f);
            v.z = fmaxf(fmaf(epsf, a.z, g.z) + pb.z, 0.f);
            v.w = fmaxf(fmaf(epsf, a.w, g.w) + pb.w, 0.f);
        }
        *(float4*)&sX[r * SX_STRIDE + c4 * 4] = v;
    }
    __syncthreads();

    float acc[8][4] = {};
    GEMM_COMPUTE_CHUNK(sX, sW)

    const float4 bv = *(const float4*)&bias[tc * 4];
#pragma unroll
    for (int i = 0; i < 8; ++i) {
        int row = row0 + tr + 16 * i;
        if (row < N_NODES) {
            float4 o;
            o.x = fmaxf(acc[i][0] + bv.x, 0.f);
            o.y = fmaxf(acc[i][1] + bv.y, 0.f);
            o.z = fmaxf(acc[i][2] + bv.z, 0.f);
            o.w = fmaxf(acc[i][3] + bv.w, 0.f);
            *(float4*)&out[(size_t)row * 64 + tc * 4] = o;
        }
    }
}

// ============================================================================
// K4: plain GEMM: out = A @ W ; tail: re-zero agg rows
// ============================================================================
__global__ void __launch_bounds__(256) gemm64_zero_kernel(
    const float* __restrict__ A, const float* __restrict__ W,
    float* __restrict__ out, float* __restrict__ aggz)
{
    extern __shared__ float smem[];
    float* sX = smem;
    float* sW = smem + TILE_ROWS * SX_STRIDE;

    const int tid = threadIdx.x;
    const int tc = tid & 15;
    const int tr = tid >> 4;
    const int row0 = blockIdx.x * TILE_ROWS;

    LOAD_W_CHUNK(sW, W)
#pragma unroll
    for (int i = 0; i < 8; ++i) {
        int f4 = tid + i * 256;
        int r = f4 >> 4, c4 = f4 & 15;
        int row = row0 + r;
        float4 v = make_float4(0.f, 0.f, 0.f, 0.f);
        if (row < N_NODES)
            v = *(const float4*)&A[(size_t)row * 64 + c4 * 4];
        *(float4*)&sX[r * SX_STRIDE + c4 * 4] = v;
    }
    __syncthreads();

    float acc[8][4] = {};
    GEMM_COMPUTE_CHUNK(sX, sW)

#pragma unroll
    for (int i = 0; i < 8; ++i) {
        int row = row0 + tr + 16 * i;
        if (row < N_NODES)
            *(float4*)&out[(size_t)row * 64 + tc * 4] =
                make_float4(acc[i][0], acc[i][1], acc[i][2], acc[i][3]);
    }

    const float4 z4 = make_float4(0.f, 0.f, 0.f, 0.f);
#pragma unroll
    for (int i = 0; i < 8; ++i) {
        int f4 = tid + i * 256;
        int row = row0 + (f4 >> 4);
        if (row < N_NODES)
            *(float4*)&aggz[(size_t)row * 64 + (f4 & 15) * 4] = z4;
    }
}

// ============================================================================
// K6: combine + GEMM + pool
// ============================================================================
__global__ void __launch_bounds__(256) combine_gemm_pool_kernel(
    const float* __restrict__ A, const float* __restrict__ G,
    const float* __restrict__ epsp, const float* __restrict__ preb,
    const float* __restrict__ W, const float* __restrict__ bias,
    const int* __restrict__ batch, float* __restrict__ pooled)
{
    extern __shared__ float smem[];
    float* sX = smem;
    float* sW = smem + TILE_ROWS * SX_STRIDE;

    const int tid = threadIdx.x;
    const int tc = tid & 15;
    const int tr = tid >> 4;
    const int row0 = blockIdx.x * TILE_ROWS;
    const float epsf = 1.0f + __ldg(&epsp[0]);

    LOAD_W_CHUNK(sW, W)
#pragma unroll
    for (int i = 0; i < 8; ++i) {
        int f4 = tid + i * 256;
        int r = f4 >> 4, c4 = f4 & 15;
        int row = row0 + r;
        float4 v = make_float4(0.f, 0.f, 0.f, 0.f);
        if (row < N_NODES) {
            float4 a = *(const float4*)&A[(size_t)row * 64 + c4 * 4];
            float4 g = *(const float4*)&G[(size_t)row * 64 + c4 * 4];
            float4 pb = *(const float4*)&preb[c4 * 4];
            v.x = fmaxf(fmaf(epsf, a.x, g.x) + pb.x, 0.f);
            v.y = fmaxf(fmaf(epsf, a.y, g.y) + pb.y, 0.f);
            v.z = fmaxf(fmaf(epsf, a.z, g.z) + pb.z, 0.f);
            v.w = fmaxf(fmaf(epsf, a.w, g.w) + pb.w, 0.f);
        }
        *(float4*)&sX[r * SX_STRIDE + c4 * 4] = v;
    }
    __syncthreads();

    float acc[8][4] = {};
    GEMM_COMPUTE_CHUNK(sX, sW)

    const float4 bv = *(const float4*)&bias[tc * 4];
#pragma unroll
    for (int i = 0; i < 8; ++i) {
        int row = row0 + tr + 16 * i;
        if (row < N_NODES) {
            int g = __ldg(&batch[row]);
            float4 o;
            o.x = fmaxf(acc[i][0] + bv.x, 0.f);
            o.y = fmaxf(acc[i][1] + bv.y, 0.f);
            o.z = fmaxf(acc[i][2] + bv.z, 0.f);
            o.w = fmaxf(acc[i][3] + bv.w, 0.f);
            float* p = pooled + (size_t)g * 64 + tc * 4;
            asm volatile("red.global.add.v4.f32 [%0], {%1,%2,%3,%4};"
                         :: "l"(p), "f"(o.x), "f"(o.y), "f"(o.z), "f"(o.w) : "memory");
        }
    }
}

// ============================================================================
// K7: head: logits + log_softmax
// ============================================================================
__global__ void __launch_bounds__(256) head_kernel(
    const float* __restrict__ pooled, const float* __restrict__ fcw,
    const float* __restrict__ fcb, float* __restrict__ out)
{
    int g = blockIdx.x * blockDim.x + threadIdx.x;
    if (g >= N_GRAPHS) return;
    float logit[OUT_CH];
#pragma unroll
    for (int j = 0; j < OUT_CH; ++j) logit[j] = __ldg(&fcb[j]);
#pragma unroll 8
    for (int k = 0; k < HID; ++k) {
        float p = pooled[g * HID + k];
#pragma unroll
        for (int j = 0; j < OUT_CH; ++j)
            logit[j] += p * __ldg(&fcw[k * OUT_CH + j]);
    }
    float m = logit[0];
#pragma unroll
    for (int j = 1; j < OUT_CH; ++j) m = fmaxf(m, logit[j]);
    float s = 0.f;
#pragma unroll
    for (int j = 0; j < OUT_CH; ++j) s += __expf(logit[j] - m);
    float ls = m + logf(s);
#pragma unroll
    for (int j = 0; j < OUT_CH; ++j) out[g * OUT_CH + j] = logit[j] - ls;
}

// ---------------- launch ----------------------------------------------------
extern "C" void kernel_launch(void* const* d_in, const int* in_sizes, int n_in,
                              void* d_out, int out_size)
{
    const float* x    = (const float*)d_in[0];
    const int*   ei   = (const int*)d_in[1];
    const int*   batch= (const int*)d_in[2];
    const float* eps0 = (const float*)d_in[3];
    const float* w0a  = (const float*)d_in[4];
    const float* b0a  = (const float*)d_in[5];
    const float* w0b  = (const float*)d_in[6];
    const float* b0b  = (const float*)d_in[7];
    const float* eps1 = (const float*)d_in[8];
    const float* w1a  = (const float*)d_in[9];
    const float* b1a  = (const float*)d_in[10];
    const float* w1b  = (const float*)d_in[11];
    const float* b1b  = (const float*)d_in[12];
    const float* fcw  = (const float*)d_in[13];
    const float* fcb  = (const float*)d_in[14];
    float*       out  = (float*)d_out;

    float *bufA, *bufB, *bufC, *pooled;
    cudaGetSymbolAddress((void**)&bufA, g_bufA);
    cudaGetSymbolAddress((void**)&bufB, g_bufB);
    cudaGetSymbolAddress((void**)&bufC, g_bufC);
    cudaGetSymbolAddress((void**)&pooled, g_pooled);

    static bool attr_done = false;
    if (!attr_done) {
        cudaFuncSetAttribute(gemm_in_kernel,
            cudaFuncAttributeMaxDynamicSharedMemorySize, SMEM_BYTES);
        cudaFuncSetAttribute(combine_gemm_kernel,
            cudaFuncAttributeMaxDynamicSharedMemorySize, SMEM_BYTES);
        cudaFuncSetAttribute(gemm64_zero_kernel,
            cudaFuncAttributeMaxDynamicSharedMemorySize, SMEM_BYTES);
        cudaFuncSetAttribute(combine_gemm_pool_kernel,
            cudaFuncAttributeMaxDynamicSharedMemorySize, SMEM_BYTES);
        attr_done = true;
    }

    const int gemm_blocks = (N_NODES + TILE_ROWS - 1) / TILE_ROWS;   // 391
    const int edge_blocks = (N_EDGES / E_PER * 16 + 255) / 256;      // 6250

    // K1: y0 = x @ w0a ; zero bufB + pooled
    gemm_in_kernel<<<gemm_blocks, 256, SMEM_BYTES>>>(x, w0a, bufA, bufB, pooled);
    // K2: agg0 = scatter-add(y0)
    edge_agg_kernel<<<edge_blocks, 256>>>(bufA, ei, bufB);
    // K3: h0 = relu(relu(combine0) @ w0b + b0b)
    combine_gemm_kernel<<<gemm_blocks, 256, SMEM_BYTES>>>(bufA, bufB, eps0, b0a, w0b, b0b, bufC);
    // K4: y1 = h0 @ w1a ; re-zero bufB
    gemm64_zero_kernel<<<gemm_blocks, 256, SMEM_BYTES>>>(bufC, w1a, bufA, bufB);
    // K5: agg1 = scatter-add(y1)
    edge_agg_kernel<<<edge_blocks, 256>>>(bufA, ei, bufB);
    // K6: h1 = relu(relu(combine1) @ w1b + b1b) ; pool into pooled
    combine_gemm_pool_kernel<<<gemm_blocks, 256, SMEM_BYTES>>>(bufA, bufB, eps1, b1a, w1b, b1b, batch, pooled);
    // K7: logits + log_softmax
    head_kernel<<<2, 256>>>(pooled, fcw, fcb, out);
}

// round 10
// speedup vs baseline: 1.4272x; 1.0368x over previous
#include <cuda_runtime.h>
#include <cstdint>

#define N_NODES  50000
#define N_EDGES  800000
#define IN_CH    128
#define HID      64
#define N_GRAPHS 512
#define OUT_CH   10

#define TILE_ROWS 128
#define SX_STRIDE 68                    // 16B-aligned, conflict-free for row-diff 1
#define SMEM_BYTES (TILE_ROWS * SX_STRIDE * 4 + 64 * 64 * 4)   // 51200

// ---------------- scratch (static device memory; no allocations) ------------
__device__ float g_bufA[N_NODES * HID];   // y (pre-agg features)
__device__ float g_bufB[N_NODES * HID];   // agg buffer (atomics target)
__device__ float g_bufC[N_NODES * HID];   // h0
__device__ float g_pooled[N_GRAPHS * HID];

// ---------------- packed f32x2 helpers --------------------------------------
#define FMA2(acc, a, b) \
    asm("fma.rn.f32x2 %0, %1, %2, %0;" : "+l"(acc) : "l"(a), "l"(b))
#define PACK2(out, x) \
    asm("mov.b64 %0, {%1, %1};" : "=l"(out) : "r"(__float_as_uint(x)))
#define UNPACK2(lo, hi, in) \
    asm("mov.b64 {%0, %1}, %2;" : "=r"(lo), "=r"(hi) : "l"(in))

// ============================================================================
// Shared GEMM core (128x64 tile, 256 threads, 8 rows x 4 cols per thread,
// accumulators as 8 x 2 packed f32x2 col-pairs -> fma.rn.f32x2, 2x fma rate)
// Thread t: cols [tc*4, tc*4+4), rows {tr + 16*i}, tc = t&15, tr = t>>4.
// ============================================================================

#define GEMM_ACC_DECL  unsigned long long acc01[8] = {}, acc23[8] = {}

#define GEMM_COMPUTE_CHUNK(sX, sW)                                            \
    _Pragma("unroll 4")                                                       \
    for (int k = 0; k < 64; k += 4) {                                         \
        ulonglong2 wv0 = *(const ulonglong2*)&sW[(k + 0) * 64 + tc * 4];      \
        ulonglong2 wv1 = *(const ulonglong2*)&sW[(k + 1) * 64 + tc * 4];      \
        ulonglong2 wv2 = *(const ulonglong2*)&sW[(k + 2) * 64 + tc * 4];      \
        ulonglong2 wv3 = *(const ulonglong2*)&sW[(k + 3) * 64 + tc * 4];      \
        _Pragma("unroll")                                                     \
        for (int i = 0; i < 8; ++i) {                                         \
            float4 xv = *(const float4*)&sX[(tr + 16 * i) * SX_STRIDE + k];   \
            unsigned long long xx;                                            \
            PACK2(xx, xv.x);                                                  \
            FMA2(acc01[i], xx, wv0.x); FMA2(acc23[i], xx, wv0.y);             \
            PACK2(xx, xv.y);                                                  \
            FMA2(acc01[i], xx, wv1.x); FMA2(acc23[i], xx, wv1.y);             \
            PACK2(xx, xv.z);                                                  \
            FMA2(acc01[i], xx, wv2.x); FMA2(acc23[i], xx, wv2.y);             \
            PACK2(xx, xv.w);                                                  \
            FMA2(acc01[i], xx, wv3.x); FMA2(acc23[i], xx, wv3.y);             \
        }                                                                     \
    }

// unpack row i's 4 accumulated columns into float4 o
#define GEMM_UNPACK_ROW(i, o)                                                 \
    {                                                                         \
        unsigned int u0, u1, u2, u3;                                          \
        UNPACK2(u0, u1, acc01[i]);                                            \
        UNPACK2(u2, u3, acc23[i]);                                            \
        o.x = __uint_as_float(u0); o.y = __uint_as_float(u1);                 \
        o.z = __uint_as_float(u2); o.w = __uint_as_float(u3);                 \
    }

// load 64x64 W chunk (row-major, contiguous) into sW via float4
#define LOAD_W_CHUNK(sW, Wptr)                                                \
    _Pragma("unroll")                                                         \
    for (int i = 0; i < 4; ++i) {                                             \
        int f4 = tid + i * 256;            /* 1024 float4s */                 \
        *(float4*)&sW[f4 * 4] = *(const float4*)&(Wptr)[f4 * 4];              \
    }

// ============================================================================
// K1: y0 = x @ w0a  (K=128). Tail: zero agg rows; block 0 zeroes pooled.
// ============================================================================
__global__ void __launch_bounds__(256) gemm_in_kernel(
    const float* __restrict__ A, const float* __restrict__ W,
    float* __restrict__ out, float* __restrict__ aggz, float* __restrict__ pooled)
{
    extern __shared__ float smem[];
    float* sX = smem;
    float* sW = smem + TILE_ROWS * SX_STRIDE;

    const int tid = threadIdx.x;
    const int tc = tid & 15;
    const int tr = tid >> 4;
    const int row0 = blockIdx.x * TILE_ROWS;

    GEMM_ACC_DECL;

    for (int kc = 0; kc < IN_CH; kc += 64) {
        LOAD_W_CHUNK(sW, W + kc * 64)
#pragma unroll
        for (int i = 0; i < 8; ++i) {
            int f4 = tid + i * 256;            // 2048 float4s = 128 rows x 16
            int r = f4 >> 4, c4 = f4 & 15;
            int row = row0 + r;
            float4 v = make_float4(0.f, 0.f, 0.f, 0.f);
            if (row < N_NODES)
                v = *(const float4*)&A[(size_t)row * IN_CH + kc + c4 * 4];
            *(float4*)&sX[r * SX_STRIDE + c4 * 4] = v;
        }
        __syncthreads();
        GEMM_COMPUTE_CHUNK(sX, sW)
        __syncthreads();
    }

#pragma unroll
    for (int i = 0; i < 8; ++i) {
        int row = row0 + tr + 16 * i;
        if (row < N_NODES) {
            float4 o;
            GEMM_UNPACK_ROW(i, o)
            *(float4*)&out[(size_t)row * 64 + tc * 4] = o;
        }
    }

    const float4 z4 = make_float4(0.f, 0.f, 0.f, 0.f);
#pragma unroll
    for (int i = 0; i < 8; ++i) {
        int f4 = tid + i * 256;
        int row = row0 + (f4 >> 4);
        if (row < N_NODES)
            *(float4*)&aggz[(size_t)row * 64 + (f4 & 15) * 4] = z4;
    }
    if (blockIdx.x == 0) {
        for (int i = tid; i < N_GRAPHS * HID / 4; i += 256)
            ((float4*)pooled)[i] = z4;
    }
}

// ============================================================================
// Edge aggregation (8 edges/thread, red.global.add.v4) — proven kernel.
// ============================================================================
#define E_PER 8
__global__ void __launch_bounds__(256) edge_agg_kernel(
    const float* __restrict__ y, const int* __restrict__ ei,
    float* __restrict__ agg)
{
    const int t = blockIdx.x * blockDim.x + threadIdx.x;
    const int c4 = t & 15;
    const int eb = (t >> 4) * E_PER;
    if (eb >= N_EDGES) return;

    int s[E_PER], d[E_PER];
#pragma unroll
    for (int j = 0; j < E_PER; ++j) {
        s[j] = __ldg(&ei[eb + j]);
        d[j] = __ldg(&ei[N_EDGES + eb + j]);
    }
    float4 v[E_PER];
#pragma unroll
    for (int j = 0; j < E_PER; ++j)
        v[j] = *(const float4*)(y + (size_t)s[j] * 64 + c4 * 4);
#pragma unroll
    for (int j = 0; j < E_PER; ++j) {
        float* p = agg + (size_t)d[j] * 64 + c4 * 4;
        asm volatile("red.global.add.v4.f32 [%0], {%1,%2,%3,%4};"
                     :: "l"(p), "f"(v[j].x), "f"(v[j].y), "f"(v[j].z), "f"(v[j].w)
                     : "memory");
    }
}

// ============================================================================
// K3: combine + GEMM:  out = relu( relu((1+eps)*A + G + preb) @ W + bias )
// ============================================================================
__global__ void __launch_bounds__(256) combine_gemm_kernel(
    const float* __restrict__ A, const float* __restrict__ G,
    const float* __restrict__ epsp, const float* __restrict__ preb,
    const float* __restrict__ W, const float* __restrict__ bias,
    float* __restrict__ out)
{
    extern __shared__ float smem[];
    float* sX = smem;
    float* sW = smem + TILE_ROWS * SX_STRIDE;

    const int tid = threadIdx.x;
    const int tc = tid & 15;
    const int tr = tid >> 4;
    const int row0 = blockIdx.x * TILE_ROWS;
    const float epsf = 1.0f + __ldg(&epsp[0]);

    LOAD_W_CHUNK(sW, W)
#pragma unroll
    for (int i = 0; i < 8; ++i) {
        int f4 = tid + i * 256;
        int r = f4 >> 4, c4 = f4 & 15;
        int row = row0 + r;
        float4 v = make_float4(0.f, 0.f, 0.f, 0.f);
        if (row < N_NODES) {
            float4 a = *(const float4*)&A[(size_t)row * 64 + c4 * 4];
            float4 g = *(const float4*)&G[(size_t)row * 64 + c4 * 4];
            float4 pb = *(const float4*)&preb[c4 * 4];
            v.x = fmaxf(fmaf(epsf, a.x, g.x) + pb.x, 0.f);
            v.y = fmaxf(fmaf(epsf, a.y, g.y) + pb.y, 0.f);
            v.z = fmaxf(fmaf(epsf, a.z, g.z) + pb.z, 0.f);
            v.w = fmaxf(fmaf(epsf, a.w, g.w) + pb.w, 0.f);
        }
        *(float4*)&sX[r * SX_STRIDE + c4 * 4] = v;
    }
    __syncthreads();

    GEMM_ACC_DECL;
    GEMM_COMPUTE_CHUNK(sX, sW)

    const float4 bv = *(const float4*)&bias[tc * 4];
#pragma unroll
    for (int i = 0; i < 8; ++i) {
        int row = row0 + tr + 16 * i;
        if (row < N_NODES) {
            float4 o;
            GEMM_UNPACK_ROW(i, o)
            o.x = fmaxf(o.x + bv.x, 0.f);
            o.y = fmaxf(o.y + bv.y, 0.f);
            o.z = fmaxf(o.z + bv.z, 0.f);
            o.w = fmaxf(o.w + bv.w, 0.f);
            *(float4*)&out[(size_t)row * 64 + tc * 4] = o;
        }
    }
}

// ============================================================================
// K4: plain GEMM: out = A @ W ; tail: re-zero agg rows
// ============================================================================
__global__ void __launch_bounds__(256) gemm64_zero_kernel(
    const float* __restrict__ A, const float* __restrict__ W,
    float* __restrict__ out, float* __restrict__ aggz)
{
    extern __shared__ float smem[];
    float* sX = smem;
    float* sW = smem + TILE_ROWS * SX_STRIDE;

    const int tid = threadIdx.x;
    const int tc = tid & 15;
    const int tr = tid >> 4;
    const int row0 = blockIdx.x * TILE_ROWS;

    LOAD_W_CHUNK(sW, W)
#pragma unroll
    for (int i = 0; i < 8; ++i) {
        int f4 = tid + i * 256;
        int r = f4 >> 4, c4 = f4 & 15;
        int row = row0 + r;
        float4 v = make_float4(0.f, 0.f, 0.f, 0.f);
        if (row < N_NODES)
            v = *(const float4*)&A[(size_t)row * 64 + c4 * 4];
        *(float4*)&sX[r * SX_STRIDE + c4 * 4] = v;
    }
    __syncthreads();

    GEMM_ACC_DECL;
    GEMM_COMPUTE_CHUNK(sX, sW)

#pragma unroll
    for (int i = 0; i < 8; ++i) {
        int row = row0 + tr + 16 * i;
        if (row < N_NODES) {
            float4 o;
            GEMM_UNPACK_ROW(i, o)
            *(float4*)&out[(size_t)row * 64 + tc * 4] = o;
        }
    }

    const float4 z4 = make_float4(0.f, 0.f, 0.f, 0.f);
#pragma unroll
    for (int i = 0; i < 8; ++i) {
        int f4 = tid + i * 256;
        int row = row0 + (f4 >> 4);
        if (row < N_NODES)
            *(float4*)&aggz[(size_t)row * 64 + (f4 & 15) * 4] = z4;
    }
}

// ============================================================================
// K6: combine + GEMM + pool
// ============================================================================
__global__ void __launch_bounds__(256) combine_gemm_pool_kernel(
    const float* __restrict__ A, const float* __restrict__ G,
    const float* __restrict__ epsp, const float* __restrict__ preb,
    const float* __restrict__ W, const float* __restrict__ bias,
    const int* __restrict__ batch, float* __restrict__ pooled)
{
    extern __shared__ float smem[];
    float* sX = smem;
    float* sW = smem + TILE_ROWS * SX_STRIDE;

    const int tid = threadIdx.x;
    const int tc = tid & 15;
    const int tr = tid >> 4;
    const int row0 = blockIdx.x * TILE_ROWS;
    const float epsf = 1.0f + __ldg(&epsp[0]);

    LOAD_W_CHUNK(sW, W)
#pragma unroll
    for (int i = 0; i < 8; ++i) {
        int f4 = tid + i * 256;
        int r = f4 >> 4, c4 = f4 & 15;
        int row = row0 + r;
        float4 v = make_float4(0.f, 0.f, 0.f, 0.f);
        if (row < N_NODES) {
            float4 a = *(const float4*)&A[(size_t)row * 64 + c4 * 4];
            float4 g = *(const float4*)&G[(size_t)row * 64 + c4 * 4];
            float4 pb = *(const float4*)&preb[c4 * 4];
            v.x = fmaxf(fmaf(epsf, a.x, g.x) + pb.x, 0.f);
            v.y = fmaxf(fmaf(epsf, a.y, g.y) + pb.y, 0.f);
            v.z = fmaxf(fmaf(epsf, a.z, g.z) + pb.z, 0.f);
            v.w = fmaxf(fmaf(epsf, a.w, g.w) + pb.w, 0.f);
        }
        *(float4*)&sX[r * SX_STRIDE + c4 * 4] = v;
    }
    __syncthreads();

    GEMM_ACC_DECL;
    GEMM_COMPUTE_CHUNK(sX, sW)

    const float4 bv = *(const float4*)&bias[tc * 4];
#pragma unroll
    for (int i = 0; i < 8; ++i) {
        int row = row0 + tr + 16 * i;
        if (row < N_NODES) {
            int g = __ldg(&batch[row]);
            float4 o;
            GEMM_UNPACK_ROW(i, o)
            o.x = fmaxf(o.x + bv.x, 0.f);
            o.y = fmaxf(o.y + bv.y, 0.f);
            o.z = fmaxf(o.z + bv.z, 0.f);
            o.w = fmaxf(o.w + bv.w, 0.f);
            float* p = pooled + (size_t)g * 64 + tc * 4;
            asm volatile("red.global.add.v4.f32 [%0], {%1,%2,%3,%4};"
                         :: "l"(p), "f"(o.x), "f"(o.y), "f"(o.z), "f"(o.w) : "memory");
        }
    }
}

// ============================================================================
// K7: head: logits + log_softmax
// ============================================================================
__global__ void __launch_bounds__(256) head_kernel(
    const float* __restrict__ pooled, const float* __restrict__ fcw,
    const float* __restrict__ fcb, float* __restrict__ out)
{
    int g = blockIdx.x * blockDim.x + threadIdx.x;
    if (g >= N_GRAPHS) return;
    float logit[OUT_CH];
#pragma unroll
    for (int j = 0; j < OUT_CH; ++j) logit[j] = __ldg(&fcb[j]);
#pragma unroll 8
    for (int k = 0; k < HID; ++k) {
        float p = pooled[g * HID + k];
#pragma unroll
        for (int j = 0; j < OUT_CH; ++j)
            logit[j] += p * __ldg(&fcw[k * OUT_CH + j]);
    }
    float m = logit[0];
#pragma unroll
    for (int j = 1; j < OUT_CH; ++j) m = fmaxf(m, logit[j]);
    float s = 0.f;
#pragma unroll
    for (int j = 0; j < OUT_CH; ++j) s += __expf(logit[j] - m);
    float ls = m + logf(s);
#pragma unroll
    for (int j = 0; j < OUT_CH; ++j) out[g * OUT_CH + j] = logit[j] - ls;
}

// ---------------- launch ----------------------------------------------------
extern "C" void kernel_launch(void* const* d_in, const int* in_sizes, int n_in,
                              void* d_out, int out_size)
{
    const float* x    = (const float*)d_in[0];
    const int*   ei   = (const int*)d_in[1];
    const int*   batch= (const int*)d_in[2];
    const float* eps0 = (const float*)d_in[3];
    const float* w0a  = (const float*)d_in[4];
    const float* b0a  = (const float*)d_in[5];
    const float* w0b  = (const float*)d_in[6];
    const float* b0b  = (const float*)d_in[7];
    const float* eps1 = (const float*)d_in[8];
    const float* w1a  = (const float*)d_in[9];
    const float* b1a  = (const float*)d_in[10];
    const float* w1b  = (const float*)d_in[11];
    const float* b1b  = (const float*)d_in[12];
    const float* fcw  = (const float*)d_in[13];
    const float* fcb  = (const float*)d_in[14];
    float*       out  = (float*)d_out;

    float *bufA, *bufB, *bufC, *pooled;
    cudaGetSymbolAddress((void**)&bufA, g_bufA);
    cudaGetSymbolAddress((void**)&bufB, g_bufB);
    cudaGetSymbolAddress((void**)&bufC, g_bufC);
    cudaGetSymbolAddress((void**)&pooled, g_pooled);

    static bool attr_done = false;
    if (!attr_done) {
        cudaFuncSetAttribute(gemm_in_kernel,
            cudaFuncAttributeMaxDynamicSharedMemorySize, SMEM_BYTES);
        cudaFuncSetAttribute(combine_gemm_kernel,
            cudaFuncAttributeMaxDynamicSharedMemorySize, SMEM_BYTES);
        cudaFuncSetAttribute(gemm64_zero_kernel,
            cudaFuncAttributeMaxDynamicSharedMemorySize, SMEM_BYTES);
        cudaFuncSetAttribute(combine_gemm_pool_kernel,
            cudaFuncAttributeMaxDynamicSharedMemorySize, SMEM_BYTES);
        attr_done = true;
    }

    const int gemm_blocks = (N_NODES + TILE_ROWS - 1) / TILE_ROWS;   // 391
    const int edge_blocks = (N_EDGES / E_PER * 16 + 255) / 256;      // 6250

    // K1: y0 = x @ w0a ; zero bufB + pooled
    gemm_in_kernel<<<gemm_blocks, 256, SMEM_BYTES>>>(x, w0a, bufA, bufB, pooled);
    // K2: agg0 = scatter-add(y0)
    edge_agg_kernel<<<edge_blocks, 256>>>(bufA, ei, bufB);
    // K3: h0 = relu(relu(combine0) @ w0b + b0b)
    combine_gemm_kernel<<<gemm_blocks, 256, SMEM_BYTES>>>(bufA, bufB, eps0, b0a, w0b, b0b, bufC);
    // K4: y1 = h0 @ w1a ; re-zero bufB
    gemm64_zero_kernel<<<gemm_blocks, 256, SMEM_BYTES>>>(bufC, w1a, bufA, bufB);
    // K5: agg1 = scatter-add(y1)
    edge_agg_kernel<<<edge_blocks, 256>>>(bufA, ei, bufB);
    // K6: h1 = relu(relu(combine1) @ w1b + b1b) ; pool into pooled
    combine_gemm_pool_kernel<<<gemm_blocks, 256, SMEM_BYTES>>>(bufA, bufB, eps1, b1a, w1b, b1b, batch, pooled);
    // K7: logits + log_softmax
    head_kernel<<<2, 256>>>(pooled, fcw, fcb, out);
}

// round 11
// speedup vs baseline: 1.4498x; 1.0158x over previous
#include <cuda_runtime.h>
#include <cstdint>

#define N_NODES  50000
#define N_EDGES  800000
#define IN_CH    128
#define HID      64
#define N_GRAPHS 512
#define OUT_CH   10

#define TILE_ROWS 64
#define NTHREADS  128
#define SX_STRIDE 68                    // 16B-aligned, conflict-free for row-diff 1
#define SMEM_BYTES (TILE_ROWS * SX_STRIDE * 4 + 64 * 64 * 4)   // 33792

// ---------------- scratch (static device memory; no allocations) ------------
__device__ float g_bufA[N_NODES * HID];   // y (pre-agg features)
__device__ float g_bufB[N_NODES * HID];   // agg buffer (atomics target)
__device__ float g_bufC[N_NODES * HID];   // h0
__device__ float g_pooled[N_GRAPHS * HID];

// ---------------- packed f32x2 helpers --------------------------------------
#define FMA2(acc, a, b) \
    asm("fma.rn.f32x2 %0, %1, %2, %0;" : "+l"(acc) : "l"(a), "l"(b))
#define PACK2(out, x) \
    asm("mov.b64 %0, {%1, %1};" : "=l"(out) : "r"(__float_as_uint(x)))
#define UNPACK2(lo, hi, in) \
    asm("mov.b64 {%0, %1}, %2;" : "=r"(lo), "=r"(hi) : "l"(in))

// ============================================================================
// Shared GEMM core (64x64 tile, 128 threads, 8 rows x 4 cols per thread,
// accumulators as 8 x 2 packed f32x2 col-pairs -> fma.rn.f32x2)
// Thread t: cols [tc*4, tc*4+4), rows {tr + 8*i}, tc = t&15, tr = t>>4 (0..7).
// ============================================================================

#define GEMM_ACC_DECL  unsigned long long acc01[8] = {}, acc23[8] = {}

#define GEMM_COMPUTE_CHUNK(sX, sW)                                            \
    _Pragma("unroll 4")                                                       \
    for (int k = 0; k < 64; k += 4) {                                         \
        ulonglong2 wv0 = *(const ulonglong2*)&sW[(k + 0) * 64 + tc * 4];      \
        ulonglong2 wv1 = *(const ulonglong2*)&sW[(k + 1) * 64 + tc * 4];      \
        ulonglong2 wv2 = *(const ulonglong2*)&sW[(k + 2) * 64 + tc * 4];      \
        ulonglong2 wv3 = *(const ulonglong2*)&sW[(k + 3) * 64 + tc * 4];      \
        _Pragma("unroll")                                                     \
        for (int i = 0; i < 8; ++i) {                                         \
            float4 xv = *(const float4*)&sX[(tr + 8 * i) * SX_STRIDE + k];    \
            unsigned long long xx;                                            \
            PACK2(xx, xv.x);                                                  \
            FMA2(acc01[i], xx, wv0.x); FMA2(acc23[i], xx, wv0.y);             \
            PACK2(xx, xv.y);                                                  \
            FMA2(acc01[i], xx, wv1.x); FMA2(acc23[i], xx, wv1.y);             \
            PACK2(xx, xv.z);                                                  \
            FMA2(acc01[i], xx, wv2.x); FMA2(acc23[i], xx, wv2.y);             \
            PACK2(xx, xv.w);                                                  \
            FMA2(acc01[i], xx, wv3.x); FMA2(acc23[i], xx, wv3.y);             \
        }                                                                     \
    }

// unpack row i's 4 accumulated columns into float4 o
#define GEMM_UNPACK_ROW(i, o)                                                 \
    {                                                                         \
        unsigned int u0, u1, u2, u3;                                          \
        UNPACK2(u0, u1, acc01[i]);                                            \
        UNPACK2(u2, u3, acc23[i]);                                            \
        o.x = __uint_as_float(u0); o.y = __uint_as_float(u1);                 \
        o.z = __uint_as_float(u2); o.w = __uint_as_float(u3);                 \
    }

// load 64x64 W chunk (row-major, contiguous) into sW via float4
#define LOAD_W_CHUNK(sW, Wptr)                                                \
    _Pragma("unroll")                                                         \
    for (int i = 0; i < 8; ++i) {                                             \
        int f4 = tid + i * NTHREADS;       /* 1024 float4s */                 \
        *(float4*)&sW[f4 * 4] = *(const float4*)&(Wptr)[f4 * 4];              \
    }

// ============================================================================
// K1: y0 = x @ w0a  (K=128). Tail: zero agg rows; block 0 zeroes pooled.
// ============================================================================
__global__ void __launch_bounds__(NTHREADS) gemm_in_kernel(
    const float* __restrict__ A, const float* __restrict__ W,
    float* __restrict__ out, float* __restrict__ aggz, float* __restrict__ pooled)
{
    extern __shared__ float smem[];
    float* sX = smem;
    float* sW = smem + TILE_ROWS * SX_STRIDE;

    const int tid = threadIdx.x;
    const int tc = tid & 15;
    const int tr = tid >> 4;
    const int row0 = blockIdx.x * TILE_ROWS;

    GEMM_ACC_DECL;

    for (int kc = 0; kc < IN_CH; kc += 64) {
        LOAD_W_CHUNK(sW, W + kc * 64)
#pragma unroll
        for (int i = 0; i < 8; ++i) {
            int f4 = tid + i * NTHREADS;       // 1024 float4s = 64 rows x 16
            int r = f4 >> 4, c4 = f4 & 15;
            int row = row0 + r;
            float4 v = make_float4(0.f, 0.f, 0.f, 0.f);
            if (row < N_NODES)
                v = *(const float4*)&A[(size_t)row * IN_CH + kc + c4 * 4];
            *(float4*)&sX[r * SX_STRIDE + c4 * 4] = v;
        }
        __syncthreads();
        GEMM_COMPUTE_CHUNK(sX, sW)
        __syncthreads();
    }

#pragma unroll
    for (int i = 0; i < 8; ++i) {
        int row = row0 + tr + 8 * i;
        if (row < N_NODES) {
            float4 o;
            GEMM_UNPACK_ROW(i, o)
            *(float4*)&out[(size_t)row * 64 + tc * 4] = o;
        }
    }

    const float4 z4 = make_float4(0.f, 0.f, 0.f, 0.f);
#pragma unroll
    for (int i = 0; i < 8; ++i) {
        int f4 = tid + i * NTHREADS;
        int row = row0 + (f4 >> 4);
        if (row < N_NODES)
            *(float4*)&aggz[(size_t)row * 64 + (f4 & 15) * 4] = z4;
    }
    if (blockIdx.x == 0) {
        for (int i = tid; i < N_GRAPHS * HID / 4; i += NTHREADS)
            ((float4*)pooled)[i] = z4;
    }
}

// ============================================================================
// Edge aggregation (8 edges/thread, red.global.add.v4) — proven kernel.
// ============================================================================
#define E_PER 8
__global__ void __launch_bounds__(256) edge_agg_kernel(
    const float* __restrict__ y, const int* __restrict__ ei,
    float* __restrict__ agg)
{
    const int t = blockIdx.x * blockDim.x + threadIdx.x;
    const int c4 = t & 15;
    const int eb = (t >> 4) * E_PER;
    if (eb >= N_EDGES) return;

    int s[E_PER], d[E_PER];
#pragma unroll
    for (int j = 0; j < E_PER; ++j) {
        s[j] = __ldg(&ei[eb + j]);
        d[j] = __ldg(&ei[N_EDGES + eb + j]);
    }
    float4 v[E_PER];
#pragma unroll
    for (int j = 0; j < E_PER; ++j)
        v[j] = *(const float4*)(y + (size_t)s[j] * 64 + c4 * 4);
#pragma unroll
    for (int j = 0; j < E_PER; ++j) {
        float* p = agg + (size_t)d[j] * 64 + c4 * 4;
        asm volatile("red.global.add.v4.f32 [%0], {%1,%2,%3,%4};"
                     :: "l"(p), "f"(v[j].x), "f"(v[j].y), "f"(v[j].z), "f"(v[j].w)
                     : "memory");
    }
}

// ============================================================================
// K3: combine + GEMM:  out = relu( relu((1+eps)*A + G + preb) @ W + bias )
// ============================================================================
__global__ void __launch_bounds__(NTHREADS) combine_gemm_kernel(
    const float* __restrict__ A, const float* __restrict__ G,
    const float* __restrict__ epsp, const float* __restrict__ preb,
    const float* __restrict__ W, const float* __restrict__ bias,
    float* __restrict__ out)
{
    extern __shared__ float smem[];
    float* sX = smem;
    float* sW = smem + TILE_ROWS * SX_STRIDE;

    const int tid = threadIdx.x;
    const int tc = tid & 15;
    const int tr = tid >> 4;
    const int row0 = blockIdx.x * TILE_ROWS;
    const float epsf = 1.0f + __ldg(&epsp[0]);

    LOAD_W_CHUNK(sW, W)
#pragma unroll
    for (int i = 0; i < 8; ++i) {
        int f4 = tid + i * NTHREADS;
        int r = f4 >> 4, c4 = f4 & 15;
        int row = row0 + r;
        float4 v = make_float4(0.f, 0.f, 0.f, 0.f);
        if (row < N_NODES) {
            float4 a = *(const float4*)&A[(size_t)row * 64 + c4 * 4];
            float4 g = *(const float4*)&G[(size_t)row * 64 + c4 * 4];
            float4 pb = *(const float4*)&preb[c4 * 4];
            v.x = fmaxf(fmaf(epsf, a.x, g.x) + pb.x, 0.f);
            v.y = fmaxf(fmaf(epsf, a.y, g.y) + pb.y, 0.f);
            v.z = fmaxf(fmaf(epsf, a.z, g.z) + pb.z, 0.f);
            v.w = fmaxf(fmaf(epsf, a.w, g.w) + pb.w, 0.f);
        }
        *(float4*)&sX[r * SX_STRIDE + c4 * 4] = v;
    }
    __syncthreads();

    GEMM_ACC_DECL;
    GEMM_COMPUTE_CHUNK(sX, sW)

    const float4 bv = *(const float4*)&bias[tc * 4];
#pragma unroll
    for (int i = 0; i < 8; ++i) {
        int row = row0 + tr + 8 * i;
        if (row < N_NODES) {
            float4 o;
            GEMM_UNPACK_ROW(i, o)
            o.x = fmaxf(o.x + bv.x, 0.f);
            o.y = fmaxf(o.y + bv.y, 0.f);
            o.z = fmaxf(o.z + bv.z, 0.f);
            o.w = fmaxf(o.w + bv.w, 0.f);
            *(float4*)&out[(size_t)row * 64 + tc * 4] = o;
        }
    }
}

// ============================================================================
// K4: plain GEMM: out = A @ W ; tail: re-zero agg rows
// ============================================================================
__global__ void __launch_bounds__(NTHREADS) gemm64_zero_kernel(
    const float* __restrict__ A, const float* __restrict__ W,
    float* __restrict__ out, float* __restrict__ aggz)
{
    extern __shared__ float smem[];
    float* sX = smem;
    float* sW = smem + TILE_ROWS * SX_STRIDE;

    const int tid = threadIdx.x;
    const int tc = tid & 15;
    const int tr = tid >> 4;
    const int row0 = blockIdx.x * TILE_ROWS;

    LOAD_W_CHUNK(sW, W)
#pragma unroll
    for (int i = 0; i < 8; ++i) {
        int f4 = tid + i * NTHREADS;
        int r = f4 >> 4, c4 = f4 & 15;
        int row = row0 + r;
        float4 v = make_float4(0.f, 0.f, 0.f, 0.f);
        if (row < N_NODES)
            v = *(const float4*)&A[(size_t)row * 64 + c4 * 4];
        *(float4*)&sX[r * SX_STRIDE + c4 * 4] = v;
    }
    __syncthreads();

    GEMM_ACC_DECL;
    GEMM_COMPUTE_CHUNK(sX, sW)

#pragma unroll
    for (int i = 0; i < 8; ++i) {
        int row = row0 + tr + 8 * i;
        if (row < N_NODES) {
            float4 o;
            GEMM_UNPACK_ROW(i, o)
            *(float4*)&out[(size_t)row * 64 + tc * 4] = o;
        }
    }

    const float4 z4 = make_float4(0.f, 0.f, 0.f, 0.f);
#pragma unroll
    for (int i = 0; i < 8; ++i) {
        int f4 = tid + i * NTHREADS;
        int row = row0 + (f4 >> 4);
        if (row < N_NODES)
            *(float4*)&aggz[(size_t)row * 64 + (f4 & 15) * 4] = z4;
    }
}

// ============================================================================
// K6: combine + GEMM + pool
// ============================================================================
__global__ void __launch_bounds__(NTHREADS) combine_gemm_pool_kernel(
    const float* __restrict__ A, const float* __restrict__ G,
    const float* __restrict__ epsp, const float* __restrict__ preb,
    const float* __restrict__ W, const float* __restrict__ bias,
    const int* __restrict__ batch, float* __restrict__ pooled)
{
    extern __shared__ float smem[];
    float* sX = smem;
    float* sW = smem + TILE_ROWS * SX_STRIDE;

    const int tid = threadIdx.x;
    const int tc = tid & 15;
    const int tr = tid >> 4;
    const int row0 = blockIdx.x * TILE_ROWS;
    const float epsf = 1.0f + __ldg(&epsp[0]);

    LOAD_W_CHUNK(sW, W)
#pragma unroll
    for (int i = 0; i < 8; ++i) {
        int f4 = tid + i * NTHREADS;
        int r = f4 >> 4, c4 = f4 & 15;
        int row = row0 + r;
        float4 v = make_float4(0.f, 0.f, 0.f, 0.f);
        if (row < N_NODES) {
            float4 a = *(const float4*)&A[(size_t)row * 64 + c4 * 4];
            float4 g = *(const float4*)&G[(size_t)row * 64 + c4 * 4];
            float4 pb = *(const float4*)&preb[c4 * 4];
            v.x = fmaxf(fmaf(epsf, a.x, g.x) + pb.x, 0.f);
            v.y = fmaxf(fmaf(epsf, a.y, g.y) + pb.y, 0.f);
            v.z = fmaxf(fmaf(epsf, a.z, g.z) + pb.z, 0.f);
            v.w = fmaxf(fmaf(epsf, a.w, g.w) + pb.w, 0.f);
        }
        *(float4*)&sX[r * SX_STRIDE + c4 * 4] = v;
    }
    __syncthreads();

    GEMM_ACC_DECL;
    GEMM_COMPUTE_CHUNK(sX, sW)

    const float4 bv = *(const float4*)&bias[tc * 4];
#pragma unroll
    for (int i = 0; i < 8; ++i) {
        int row = row0 + tr + 8 * i;
        if (row < N_NODES) {
            int g = __ldg(&batch[row]);
            float4 o;
            GEMM_UNPACK_ROW(i, o)
            o.x = fmaxf(o.x + bv.x, 0.f);
            o.y = fmaxf(o.y + bv.y, 0.f);
            o.z = fmaxf(o.z + bv.z, 0.f);
            o.w = fmaxf(o.w + bv.w, 0.f);
            float* p = pooled + (size_t)g * 64 + tc * 4;
            asm volatile("red.global.add.v4.f32 [%0], {%1,%2,%3,%4};"
                         :: "l"(p), "f"(o.x), "f"(o.y), "f"(o.z), "f"(o.w) : "memory");
        }
    }
}

// ============================================================================
// K7: head: logits + log_softmax
// ============================================================================
__global__ void __launch_bounds__(256) head_kernel(
    const float* __restrict__ pooled, const float* __restrict__ fcw,
    const float* __restrict__ fcb, float* __restrict__ out)
{
    int g = blockIdx.x * blockDim.x + threadIdx.x;
    if (g >= N_GRAPHS) return;
    float logit[OUT_CH];
#pragma unroll
    for (int j = 0; j < OUT_CH; ++j) logit[j] = __ldg(&fcb[j]);
#pragma unroll 8
    for (int k = 0; k < HID; ++k) {
        float p = pooled[g * HID + k];
#pragma unroll
        for (int j = 0; j < OUT_CH; ++j)
            logit[j] += p * __ldg(&fcw[k * OUT_CH + j]);
    }
    float m = logit[0];
#pragma unroll
    for (int j = 1; j < OUT_CH; ++j) m = fmaxf(m, logit[j]);
    float s = 0.f;
#pragma unroll
    for (int j = 0; j < OUT_CH; ++j) s += __expf(logit[j] - m);
    float ls = m + logf(s);
#pragma unroll
    for (int j = 0; j < OUT_CH; ++j) out[g * OUT_CH + j] = logit[j] - ls;
}

// ---------------- launch ----------------------------------------------------
extern "C" void kernel_launch(void* const* d_in, const int* in_sizes, int n_in,
                              void* d_out, int out_size)
{
    const float* x    = (const float*)d_in[0];
    const int*   ei   = (const int*)d_in[1];
    const int*   batch= (const int*)d_in[2];
    const float* eps0 = (const float*)d_in[3];
    const float* w0a  = (const float*)d_in[4];
    const float* b0a  = (const float*)d_in[5];
    const float* w0b  = (const float*)d_in[6];
    const float* b0b  = (const float*)d_in[7];
    const float* eps1 = (const float*)d_in[8];
    const float* w1a  = (const float*)d_in[9];
    const float* b1a  = (const float*)d_in[10];
    const float* w1b  = (const float*)d_in[11];
    const float* b1b  = (const float*)d_in[12];
    const float* fcw  = (const float*)d_in[13];
    const float* fcb  = (const float*)d_in[14];
    float*       out  = (float*)d_out;

    float *bufA, *bufB, *bufC, *pooled;
    cudaGetSymbolAddress((void**)&bufA, g_bufA);
    cudaGetSymbolAddress((void**)&bufB, g_bufB);
    cudaGetSymbolAddress((void**)&bufC, g_bufC);
    cudaGetSymbolAddress((void**)&pooled, g_pooled);

    static bool attr_done = false;
    if (!attr_done) {
        cudaFuncSetAttribute(gemm_in_kernel,
            cudaFuncAttributeMaxDynamicSharedMemorySize, SMEM_BYTES);
        cudaFuncSetAttribute(combine_gemm_kernel,
            cudaFuncAttributeMaxDynamicSharedMemorySize, SMEM_BYTES);
        cudaFuncSetAttribute(gemm64_zero_kernel,
            cudaFuncAttributeMaxDynamicSharedMemorySize, SMEM_BYTES);
        cudaFuncSetAttribute(combine_gemm_pool_kernel,
            cudaFuncAttributeMaxDynamicSharedMemorySize, SMEM_BYTES);
        attr_done = true;
    }

    const int gemm_blocks = (N_NODES + TILE_ROWS - 1) / TILE_ROWS;   // 782
    const int edge_blocks = (N_EDGES / E_PER * 16 + 255) / 256;      // 6250

    // K1: y0 = x @ w0a ; zero bufB + pooled
    gemm_in_kernel<<<gemm_blocks, NTHREADS, SMEM_BYTES>>>(x, w0a, bufA, bufB, pooled);
    // K2: agg0 = scatter-add(y0)
    edge_agg_kernel<<<edge_blocks, 256>>>(bufA, ei, bufB);
    // K3: h0 = relu(relu(combine0) @ w0b + b0b)
    combine_gemm_kernel<<<gemm_blocks, NTHREADS, SMEM_BYTES>>>(bufA, bufB, eps0, b0a, w0b, b0b, bufC);
    // K4: y1 = h0 @ w1a ; re-zero bufB
    gemm64_zero_kernel<<<gemm_blocks, NTHREADS, SMEM_BYTES>>>(bufC, w1a, bufA, bufB);
    // K5: agg1 = scatter-add(y1)
    edge_agg_kernel<<<edge_blocks, 256>>>(bufA, ei, bufB);
    // K6: h1 = relu(relu(combine1) @ w1b + b1b) ; pool into pooled
    combine_gemm_pool_kernel<<<gemm_blocks, NTHREADS, SMEM_BYTES>>>(bufA, bufB, eps1, b1a, w1b, b1b, batch, pooled);
    // K7: logits + log_softmax
    head_kernel<<<2, 256>>>(pooled, fcw, fcb, out);
}